// round 8
// baseline (speedup 1.0000x reference)
#include <cuda_runtime.h>
#include <stdint.h>

#define Bc    64
#define CIN   256
#define COUT  256
#define HW    28
#define NPIX  (HW*HW)            // 784
#define NW    (COUT*CIN*9)       // 589824
#define KK    8
#define PDIM  30
#define PPIX  (PDIM*PDIM)        // 900

// ---------------- device scratch ----------------
__device__ __align__(16) uint32_t g_w[COUT * 9 * 8];          // [o][t][cw] sign bits
__device__ int                    g_corr[COUT * 9];           // 256 - 2*popc(w[o][t])
__device__ __align__(16) uint32_t g_pabits[(size_t)Bc * PPIX * 8]; // padded bit image

// ---------------------------------------------------------------------------
// Kernel 1: weights -> packed sign bits + pad corrections.
// Coalesced stride-256 loads, smem transpose, ballot pack. grid <<<256,256>>>
// ---------------------------------------------------------------------------
__global__ void wbits_kernel(const float* __restrict__ M, const float* __restrict__ Z,
                             const float* __restrict__ rv)
{
    __shared__ float swv[2304];
    __shared__ int   sP[9];
    const int o    = blockIdx.x;
    const int c    = threadIdx.x;
    const int lane = c & 31;
    const int cw   = c >> 5;

    if (c < 9) sP[c] = 0;

    float rvl[KK];
#pragma unroll
    for (int k = 0; k < KK; k++) rvl[k] = __ldg(rv + k);

    // thread c owns flat elements i*256+c of this o's 2304-float slice
    float wv9[9];
    {
        const float* Mp = M + (size_t)o * 2304;
#pragma unroll
        for (int i = 0; i < 9; i++) wv9[i] = Mp[i * 256 + c];
#pragma unroll
        for (int k = 0; k < KK; k++) {
            const float* zp = Z + (size_t)k * NW + (size_t)o * 2304;
#pragma unroll
            for (int i = 0; i < 9; i++) wv9[i] += rvl[k] * zp[i * 256 + c];
        }
    }
#pragma unroll
    for (int i = 0; i < 9; i++) swv[i * 256 + c] = wv9[i];
    __syncthreads();

    // thread c = input channel c; its 9 taps are swv[c*9 .. c*9+8] (stride 9: conflict-free)
#pragma unroll
    for (int j = 0; j < 9; j++) {
        unsigned bit  = __float_as_uint(swv[c * 9 + j]) >> 31;
        unsigned mask = __ballot_sync(0xffffffffu, bit);
        if (lane == 0) {
            g_w[(o * 9 + j) * 8 + cw] = mask;
            atomicAdd(&sP[j], __popc(mask));
        }
    }
    __syncthreads();
    if (c < 9) g_corr[o * 9 + c] = 256 - 2 * sP[c];
}

// ---------------------------------------------------------------------------
// Kernel 2: activations -> zero-padded packed bit image [b][pp][8]
// grid <<<225, 256>>>
// ---------------------------------------------------------------------------
__global__ void abits_kernel(const float* __restrict__ x)
{
    const int gid = blockIdx.x * 256 + threadIdx.x;
    const int b  = gid / PPIX;
    const int pp = gid - b * PPIX;
    const int py = pp / PDIM;
    const int px = pp - py * PDIM;

    uint4* dst = (uint4*)(g_pabits + ((size_t)b * PPIX + pp) * 8);

    if (py == 0 || py == PDIM - 1 || px == 0 || px == PDIM - 1) {
        uint4 z = make_uint4(0, 0, 0, 0);
        dst[0] = z; dst[1] = z;
        return;
    }
    const float* xp = x + (size_t)b * CIN * NPIX + (py - 1) * HW + (px - 1);
    uint32_t w[8];
#pragma unroll
    for (int cw = 0; cw < 8; cw++) {
        uint32_t m = 0;
#pragma unroll
        for (int j = 0; j < 32; j++) {
            uint32_t s = __float_as_uint(xp[(size_t)(cw * 32 + j) * NPIX]) >> 31;
            m |= s << j;
        }
        w[cw] = m;
    }
    dst[0] = make_uint4(w[0], w[1], w[2], w[3]);
    dst[1] = make_uint4(w[4], w[5], w[6], w[7]);
}

// ---------------------------------------------------------------------------
// Kernel 3: XNOR-popcount conv, one output row per CTA.
// Row-structured: each activation pixel loaded once, applied to 3 kw taps.
// 8 warps; warp = 32-outch group, lane = outch. grid <<<1792, 256, 32576>>>
// ---------------------------------------------------------------------------
#define SM_ABITS 0                      // 3 rows x 30 px x 32B = 2880
#define SM_STAGE 2880                   // 8 warps x 32 x 29 floats = 29696
#define SM_TOTAL (2880 + 29696)

#define P8(A0, A1, W0, W1) \
    (__popc((A0).x ^ (W0).x) + __popc((A0).y ^ (W0).y) + \
     __popc((A0).z ^ (W0).z) + __popc((A0).w ^ (W0).w) + \
     __popc((A1).x ^ (W1).x) + __popc((A1).y ^ (W1).y) + \
     __popc((A1).z ^ (W1).z) + __popc((A1).w ^ (W1).w))

__global__ void __launch_bounds__(256)
conv_pop_kernel(const float* __restrict__ alpha, float* __restrict__ out)
{
    extern __shared__ __align__(16) uint8_t smem[];

    const int tid  = threadIdx.x;
    const int wid  = tid >> 5;
    const int lane = tid & 31;

    const int b = blockIdx.x / HW;
    const int y = blockIdx.x - b * HW;

    // cooperative load: padded rows y..y+2 (contiguous, 180 uint4)
    {
        const uint4* src = (const uint4*)(g_pabits + ((size_t)b * PPIX + y * PDIM) * 8);
        uint4* d4 = (uint4*)(smem + SM_ABITS);
        if (tid < 180) d4[tid] = src[tid];
    }

    const int o = wid * 32 + lane;
    int corr[9];
#pragma unroll
    for (int t = 0; t < 9; t++) corr[t] = __ldg(g_corr + o * 9 + t);
    const float av = __ldg(alpha + o);
    const uint4* wbase = (const uint4*)(g_w + o * 72);

    __syncthreads();

    const uint32_t* ab = (const uint32_t*)(smem + SM_ABITS);
    float* stage = (float*)(smem + SM_STAGE) + wid * (32 * 29);

    int acc[28];
#pragma unroll
    for (int x = 0; x < 28; x++) acc[x] = 0;

    const uint4* wp = wbase;
#pragma unroll 1
    for (int kh = 0; kh < 3; kh++) {
        const uint4 w00 = __ldg(wp + 0), w01 = __ldg(wp + 1);   // kw=0
        const uint4 w10 = __ldg(wp + 2), w11 = __ldg(wp + 3);   // kw=1
        const uint4 w20 = __ldg(wp + 4), w21 = __ldg(wp + 5);   // kw=2
        wp += 6;
        const uint4* rowp = (const uint4*)(ab + kh * PDIM * 8);
#pragma unroll
        for (int px = 0; px < 30; px++) {
            const uint4 a0 = rowp[px * 2];
            const uint4 a1 = rowp[px * 2 + 1];
            if (px < 28)             acc[px]     += P8(a0, a1, w00, w01);
            if (px >= 1 && px <= 28) acc[px - 1] += P8(a0, a1, w10, w11);
            if (px >= 2)             acc[px - 2] += P8(a0, a1, w20, w21);
        }
    }

    // pad corrections (row-uniform + column edges)
    const int rowc = (y == 0)  ? (corr[0] + corr[1] + corr[2])
                   : (y == 27) ? (corr[6] + corr[7] + corr[8]) : 0;
    int c0  = corr[0] + corr[3] + corr[6];
    int c27 = corr[2] + corr[5] + corr[8];
    if (y == 0)  { c0 -= corr[0]; c27 -= corr[2]; }
    if (y == 27) { c0 -= corr[6]; c27 -= corr[8]; }

#pragma unroll
    for (int x = 0; x < 28; x++) {
        int cs = rowc;
        if (x == 0)  cs += c0;
        if (x == 27) cs += c27;
        stage[lane * 29 + x] = av * (float)(2304 - 2 * acc[x] - cs);
    }

    __syncwarp();
    float* outb = out + ((size_t)(b * COUT + wid * 32) * HW + y) * HW;
    if (lane < HW) {
#pragma unroll 4
        for (int oo = 0; oo < 32; oo++)
            outb[(size_t)oo * NPIX + lane] = stage[oo * 29 + lane];
    }
}

// ---------------------------------------------------------------------------
extern "C" void kernel_launch(void* const* d_in, const int* in_sizes, int n_in,
                              void* d_out, int out_size)
{
    const float* x  = (const float*)d_in[0];
    const float* M  = (const float*)d_in[1];
    const float* Z  = (const float*)d_in[2];
    const float* al = (const float*)d_in[3];
    const float* rv = (const float*)d_in[4];

    cudaFuncSetAttribute(conv_pop_kernel,
                         cudaFuncAttributeMaxDynamicSharedMemorySize, SM_TOTAL);

    wbits_kernel<<<COUT, CIN>>>(M, Z, rv);
    abits_kernel<<<225, 256>>>(x);
    conv_pop_kernel<<<Bc * HW, 256, SM_TOTAL>>>(al, (float*)d_out);
}